// round 14
// baseline (speedup 1.0000x reference)
#include <cuda_runtime.h>
#include <cuda_bf16.h>
#include <cuda_fp16.h>
#include <math.h>
#include <stdint.h>

// ---------------- problem constants ----------------
#define BB   4
#define NN   512
#define DD   1024
#define HH   16
#define HD   64
#define HID  4096
#define TOK  (BB*NN)      // 2048
#define MODD (6*DD)       // 6144

// ---------------- scratch (static device globals) ----------------
__device__ float g_mod[BB*MODD];
__device__ float g_silu[BB*DD];
__device__ unsigned short g_xn_h[TOK*DD], g_xn_l[TOK*DD];  // bf16 h/l (ln1) or fp16 (ln2 in h)
__device__ unsigned short g_xn_f[TOK*DD];                  // fp16 single (ln1, for V)
__device__ __nv_bfloat16 g_q_h[TOK*DD], g_q_l[TOK*DD];
__device__ __nv_bfloat16 g_k_h[TOK*DD], g_k_l[TOK*DD];
__device__ unsigned short g_v_f[TOK*DD];                   // fp16 single
__device__ __nv_bfloat16 g_biasb[(size_t)BB*HH*NN*NN];     // 32 MB bf16
__device__ unsigned short g_ao_h[TOK*DD];                  // fp16 single
__device__ float g_x1[TOK*DD];
__device__ float g_part0[TOK*DD], g_part1[TOK*DD];
__device__ unsigned short g_hbuf[(size_t)TOK*HID];         // fp16 single
__device__ __nv_bfloat16 g_wqk_h[2*DD*DD], g_wqk_l[2*DD*DD];
__device__ unsigned short g_wv_f[DD*DD];
__device__ unsigned short g_wp_f[DD*DD];
__device__ unsigned short g_w1_f[(size_t)HID*DD];
__device__ unsigned short g_w2_f[(size_t)DD*HID];

// ---------------- helpers ----------------
__device__ __forceinline__ uint32_t smem_u32(const void* p) {
    uint32_t a;
    asm("{ .reg .u64 t; cvta.to.shared.u64 t, %1; cvt.u32.u64 %0, t; }" : "=r"(a) : "l"(p));
    return a;
}
__device__ __forceinline__ unsigned short bfbits(__nv_bfloat16 v) {
    return *reinterpret_cast<unsigned short*>(&v);
}
__device__ __forceinline__ unsigned short hfbits(__half v) {
    return *reinterpret_cast<unsigned short*>(&v);
}
__device__ __forceinline__ uint32_t packhf(float a, float b) {
    return (uint32_t)hfbits(__float2half_rn(a)) | ((uint32_t)hfbits(__float2half_rn(b)) << 16);
}

#define LDSM4(r, addr) \
    asm volatile("ldmatrix.sync.aligned.m8n8.x4.shared.b16 {%0,%1,%2,%3}, [%4];" \
        : "=r"((r)[0]), "=r"((r)[1]), "=r"((r)[2]), "=r"((r)[3]) : "r"(addr))
#define LDSM4T(r, addr) \
    asm volatile("ldmatrix.sync.aligned.m8n8.x4.trans.shared.b16 {%0,%1,%2,%3}, [%4];" \
        : "=r"((r)[0]), "=r"((r)[1]), "=r"((r)[2]), "=r"((r)[3]) : "r"(addr))

#define MMA16816(d, a, b) \
    asm volatile("mma.sync.aligned.m16n8k16.row.col.f32.bf16.bf16.f32 " \
        "{%0,%1,%2,%3}, {%4,%5,%6,%7}, {%8,%9}, {%0,%1,%2,%3};" \
        : "+f"((d)[0]), "+f"((d)[1]), "+f"((d)[2]), "+f"((d)[3]) \
        : "r"((a)[0]), "r"((a)[1]), "r"((a)[2]), "r"((a)[3]), \
          "r"((b)[0]), "r"((b)[1]))
#define MMAF16(d, a, b) \
    asm volatile("mma.sync.aligned.m16n8k16.row.col.f32.f16.f16.f32 " \
        "{%0,%1,%2,%3}, {%4,%5,%6,%7}, {%8,%9}, {%0,%1,%2,%3};" \
        : "+f"((d)[0]), "+f"((d)[1]), "+f"((d)[2]), "+f"((d)[3]) \
        : "r"((a)[0]), "r"((a)[1]), "r"((a)[2]), "r"((a)[3]), \
          "r"((b)[0]), "r"((b)[1]))

#define CP16(dst, src) \
    asm volatile("cp.async.cg.shared.global [%0], [%1], 16;" :: "r"(dst), "l"(src) : "memory")
#define CP_COMMIT() asm volatile("cp.async.commit_group;" ::: "memory")
#define CP_WAIT1()  asm volatile("cp.async.wait_group 1;" ::: "memory")
#define CP_WAIT0()  asm volatile("cp.async.wait_group 0;" ::: "memory")

// ---------------- weight conversions (split for overlap) ----------------
#define QK_F4 (2*DD*DD/4)
__global__ void k_cvtqk(const float4* __restrict__ wqkv) {
    for (size_t i = blockIdx.x * blockDim.x + threadIdx.x; i < QK_F4;
         i += (size_t)gridDim.x * blockDim.x) {
        float4 v = wqkv[i];
        float vv[4] = {v.x, v.y, v.z, v.w};
        union { unsigned short u[4]; uint2 d; } H, L;
        #pragma unroll
        for (int j = 0; j < 4; j++) {
            __nv_bfloat16 hb = __float2bfloat16(vv[j]);
            H.u[j] = bfbits(hb);
            L.u[j] = bfbits(__float2bfloat16(vv[j] - __bfloat162float(hb)));
        }
        ((uint2*)g_wqk_h)[i] = H.d;
        ((uint2*)g_wqk_l)[i] = L.d;
    }
}
#define V_F4  (DD*DD/4)
#define WP_F4 (DD*DD/4)
#define W1_F4 ((size_t)HID*DD/4)
#define REST_TOTAL (V_F4 + WP_F4 + 2*W1_F4)
__global__ void k_cvtrest(const float4* __restrict__ wqkv, const float4* __restrict__ wp,
                          const float4* __restrict__ w1, const float4* __restrict__ w2) {
    for (size_t i = blockIdx.x * blockDim.x + threadIdx.x; i < REST_TOTAL;
         i += (size_t)gridDim.x * blockDim.x) {
        const float4* src;
        uint2* dst;
        size_t j;
        if (i < V_F4) {
            j = i; src = wqkv + QK_F4 + j; dst = (uint2*)g_wv_f;
        } else if (i < V_F4 + WP_F4) {
            j = i - V_F4; src = wp + j; dst = (uint2*)g_wp_f;
        } else if (i < V_F4 + WP_F4 + W1_F4) {
            j = i - V_F4 - WP_F4; src = w1 + j; dst = (uint2*)g_w1_f;
        } else {
            j = i - V_F4 - WP_F4 - W1_F4; src = w2 + j; dst = (uint2*)g_w2_f;
        }
        float4 v = *src;
        union { unsigned short u[4]; uint2 d; } H;
        H.u[0] = hfbits(__float2half_rn(v.x));
        H.u[1] = hfbits(__float2half_rn(v.y));
        H.u[2] = hfbits(__float2half_rn(v.z));
        H.u[3] = hfbits(__float2half_rn(v.w));
        dst[j] = H.d;
    }
}

// ---------------- silu precompute + adaLN modulation ----------------
__global__ void k_silu(const float* __restrict__ t_emb) {
    int i = blockIdx.x * blockDim.x + threadIdx.x;
    if (i < BB * DD) {
        float t = t_emb[i];
        g_silu[i] = t / (1.f + __expf(-t));
    }
}
__global__ void k_mod(const float* __restrict__ w_ada,
                      const float* __restrict__ b_ada) {
    int warp = (blockIdx.x * blockDim.x + threadIdx.x) >> 5;
    int lane = threadIdx.x & 31;
    if (warp >= BB * MODD) return;
    int b = warp / MODD, o = warp % MODD;
    const float* te = g_silu + b * DD;
    const float* w  = w_ada + (size_t)o * DD;
    float acc = 0.f;
    #pragma unroll 8
    for (int k = lane; k < DD; k += 32)
        acc = fmaf(te[k], w[k], acc);
    #pragma unroll
    for (int off = 16; off; off >>= 1)
        acc += __shfl_xor_sync(0xffffffffu, acc, off);
    if (lane == 0) g_mod[b * MODD + o] = acc + b_ada[o];
}

// ---------------- LayerNorm1 + modulate -> bf16 hi/lo + fp16 ----------------
__global__ void k_ln_mod(const float* __restrict__ x,
                         const float* __restrict__ g,
                         const float* __restrict__ beta,
                         int shift_off, int scale_off,
                         unsigned short* __restrict__ oh,
                         unsigned short* __restrict__ ol,
                         unsigned short* __restrict__ of) {
    int t = blockIdx.x;
    int b = t >> 9;
    const float* xr = x + (size_t)t * DD;
    float v[4];
    float s = 0.f, ss = 0.f;
    #pragma unroll
    for (int i = 0; i < 4; i++) {
        v[i] = xr[threadIdx.x + i * 256];
        s += v[i]; ss += v[i] * v[i];
    }
    __shared__ float shs[8], shss[8];
    #pragma unroll
    for (int o = 16; o; o >>= 1) {
        s  += __shfl_xor_sync(0xffffffffu, s,  o);
        ss += __shfl_xor_sync(0xffffffffu, ss, o);
    }
    int w = threadIdx.x >> 5, l = threadIdx.x & 31;
    if (l == 0) { shs[w] = s; shss[w] = ss; }
    __syncthreads();
    if (w == 0) {
        s  = (l < 8) ? shs[l]  : 0.f;
        ss = (l < 8) ? shss[l] : 0.f;
        #pragma unroll
        for (int o = 4; o; o >>= 1) {
            s  += __shfl_xor_sync(0xffffffffu, s,  o);
            ss += __shfl_xor_sync(0xffffffffu, ss, o);
        }
        if (l == 0) { shs[0] = s; shss[0] = ss; }
    }
    __syncthreads();
    float mu  = shs[0] * (1.f / DD);
    float var = shss[0] * (1.f / DD) - mu * mu;
    float r   = rsqrtf(var + 1e-5f);
    const float* shiftp = g_mod + b * MODD + shift_off;
    const float* scalep = g_mod + b * MODD + scale_off;
    #pragma unroll
    for (int i = 0; i < 4; i++) {
        int d = threadIdx.x + i * 256;
        float xn = (v[i] - mu) * r * g[d] + beta[d];
        float o = xn * (1.f + scalep[d]) + shiftp[d];
        size_t idx = (size_t)t * DD + d;
        __nv_bfloat16 hb = __float2bfloat16(o);
        oh[idx] = bfbits(hb);
        ol[idx] = bfbits(__float2bfloat16(o - __bfloat162float(hb)));
        of[idx] = hfbits(__float2half_rn(o));
    }
}

// ---------------- fused proj-combine + LayerNorm2 -> fp16 ----------------
__global__ void k_comb_ln(const float4* __restrict__ p0, const float4* __restrict__ p1,
                          const float* __restrict__ bias, const float4* __restrict__ xin,
                          int gate_off,
                          const float* __restrict__ g, const float* __restrict__ beta,
                          int shift_off, int scale_off,
                          float4* __restrict__ x1out, unsigned short* __restrict__ oh) {
    int t = blockIdx.x, b = t >> 9, tid = threadIdx.x;
    int i4 = t * 256 + tid;
    int gn = tid * 4;
    const float* gate = g_mod + b * MODD + gate_off;
    float4 a = p0[i4], c = p1[i4], r = xin[i4];
    float4 v;
    v.x = r.x + gate[gn + 0] * (a.x + c.x + bias[gn + 0]);
    v.y = r.y + gate[gn + 1] * (a.y + c.y + bias[gn + 1]);
    v.z = r.z + gate[gn + 2] * (a.z + c.z + bias[gn + 2]);
    v.w = r.w + gate[gn + 3] * (a.w + c.w + bias[gn + 3]);
    x1out[i4] = v;
    float s  = v.x + v.y + v.z + v.w;
    float ss = v.x * v.x + v.y * v.y + v.z * v.z + v.w * v.w;
    __shared__ float shs[8], shss[8];
    #pragma unroll
    for (int o = 16; o; o >>= 1) {
        s  += __shfl_xor_sync(0xffffffffu, s,  o);
        ss += __shfl_xor_sync(0xffffffffu, ss, o);
    }
    int w = tid >> 5, l = tid & 31;
    if (l == 0) { shs[w] = s; shss[w] = ss; }
    __syncthreads();
    if (w == 0) {
        s  = (l < 8) ? shs[l]  : 0.f;
        ss = (l < 8) ? shss[l] : 0.f;
        #pragma unroll
        for (int o = 4; o; o >>= 1) {
            s  += __shfl_xor_sync(0xffffffffu, s,  o);
            ss += __shfl_xor_sync(0xffffffffu, ss, o);
        }
        if (l == 0) { shs[0] = s; shss[0] = ss; }
    }
    __syncthreads();
    float mu  = shs[0] * (1.f / DD);
    float var = shss[0] * (1.f / DD) - mu * mu;
    float rin = rsqrtf(var + 1e-5f);
    const float* shiftp = g_mod + b * MODD + shift_off;
    const float* scalep = g_mod + b * MODD + scale_off;
    float vv[4] = {v.x, v.y, v.z, v.w};
    union { unsigned short u[4]; uint2 d2; } H;
    #pragma unroll
    for (int j = 0; j < 4; j++) {
        int d = gn + j;
        float xn = (vv[j] - mu) * rin * g[d] + beta[d];
        float o = xn * (1.f + scalep[d]) + shiftp[d];
        H.u[j] = hfbits(__float2half_rn(o));
    }
    *(uint2*)(oh + (size_t)t * DD + gn) = H.d2;
}

// ---------------- HMMA bf16x3 GEMM (Q,K projection), 256x128 tile ---------
#define SA_H 0
#define SA_L 20480
#define SB_H 40960
#define SB_L 51200
#define STG2 61440
#define SMEM2 (3*STG2)

__global__ void __launch_bounds__(512, 1)
k_hmma2(const __nv_bfloat16* __restrict__ Ahp, const __nv_bfloat16* __restrict__ Alp,
        const __nv_bfloat16* __restrict__ Whp, const __nv_bfloat16* __restrict__ Wlp,
        const float* __restrict__ bias, int Kfull, int N) {
    extern __shared__ char smem[];
    uint32_t sb = smem_u32(smem);
    const int tid = threadIdx.x, lane = tid & 31, wid = tid >> 5;
    const int warp_m = wid & 3, warp_n = wid >> 2;
    const int row0 = blockIdx.y * 256, col0 = blockIdx.x * 128;
    const int Kb = Kfull * 2;

    const char* gA0 = (const char*)Ahp + (size_t)row0 * Kb;
    const char* gA1 = (const char*)Alp + (size_t)row0 * Kb;
    const char* gB0 = (const char*)Whp + (size_t)col0 * Kb;
    const char* gB1 = (const char*)Wlp + (size_t)col0 * Kb;

    const int arow = tid >> 2, acol = (tid & 3) * 16;
    const uint32_t aOff = (uint32_t)((warp_m * 64 + (lane & 15)) * 80
                                     + ((lane >> 4) & 1) * 16);
    const uint32_t bOff = (uint32_t)((warp_n * 32 + (lane & 7) + ((lane >> 4) & 1) * 8) * 80
                                     + ((lane >> 3) & 1) * 16);

    float acc[4][4][4] = {};
    const int stages = Kfull >> 5;

    #define ISSUE2(s) do { \
        uint32_t dbase = sb + ((s) % 3) * STG2; \
        size_t kbyte = (size_t)(s) * 64; \
        CP16(dbase + SA_H + arow * 80 + acol,          gA0 + (size_t)arow * Kb + kbyte + acol); \
        CP16(dbase + SA_H + (arow + 128) * 80 + acol,  gA0 + (size_t)(arow + 128) * Kb + kbyte + acol); \
        CP16(dbase + SA_L + arow * 80 + acol,          gA1 + (size_t)arow * Kb + kbyte + acol); \
        CP16(dbase + SA_L + (arow + 128) * 80 + acol,  gA1 + (size_t)(arow + 128) * Kb + kbyte + acol); \
        CP16(dbase + SB_H + arow * 80 + acol,          gB0 + (size_t)arow * Kb + kbyte + acol); \
        CP16(dbase + SB_L + arow * 80 + acol,          gB1 + (size_t)arow * Kb + kbyte + acol); \
    } while (0)

    ISSUE2(0); CP_COMMIT();
    if (stages > 1) ISSUE2(1);
    CP_COMMIT();

    for (int s = 0; s < stages; s++) {
        CP_WAIT1();
        __syncthreads();
        if (s + 2 < stages) ISSUE2(s + 2);
        CP_COMMIT();

        uint32_t base = sb + (s % 3) * STG2;
        #pragma unroll
        for (int ko = 0; ko < 2; ko++) {
            uint32_t koff = ko * 32;
            uint32_t Ahf[4][4];
            #pragma unroll
            for (int fm = 0; fm < 4; fm++)
                LDSM4(Ahf[fm], base + SA_H + aOff + fm * 16 * 80 + koff);
            uint32_t Bhf[2][4];
            #pragma unroll
            for (int p = 0; p < 2; p++)
                LDSM4(Bhf[p], base + SB_H + bOff + p * 16 * 80 + koff);
            #pragma unroll
            for (int fm = 0; fm < 4; fm++)
                #pragma unroll
                for (int fn = 0; fn < 4; fn++)
                    MMA16816(acc[fm][fn], Ahf[fm], &Bhf[fn >> 1][(fn & 1) * 2]);
            {
                uint32_t Alf[4][4];
                #pragma unroll
                for (int fm = 0; fm < 4; fm++)
                    LDSM4(Alf[fm], base + SA_L + aOff + fm * 16 * 80 + koff);
                #pragma unroll
                for (int fm = 0; fm < 4; fm++)
                    #pragma unroll
                    for (int fn = 0; fn < 4; fn++)
                        MMA16816(acc[fm][fn], Alf[fm], &Bhf[fn >> 1][(fn & 1) * 2]);
            }
            {
                uint32_t Blf[2][4];
                #pragma unroll
                for (int p = 0; p < 2; p++)
                    LDSM4(Blf[p], base + SB_L + bOff + p * 16 * 80 + koff);
                #pragma unroll
                for (int fm = 0; fm < 4; fm++)
                    #pragma unroll
                    for (int fn = 0; fn < 4; fn++)
                        MMA16816(acc[fm][fn], Ahf[fm], &Blf[fn >> 1][(fn & 1) * 2]);
            }
        }
        __syncthreads();
    }

    // epilogue: q/k scatter -> per-head bf16 hi/lo
    const int mrow = lane >> 2, ncol = (lane & 3) * 2;
    #pragma unroll
    for (int fm = 0; fm < 4; fm++) {
        #pragma unroll
        for (int fn = 0; fn < 4; fn++) {
            #pragma unroll
            for (int half = 0; half < 2; half++) {
                int gm = row0 + warp_m * 64 + fm * 16 + mrow + half * 8;
                int gn = col0 + warp_n * 32 + fn * 8 + ncol;
                float v0 = acc[fm][fn][half * 2 + 0] + bias[gn];
                float v1 = acc[fm][fn][half * 2 + 1] + bias[gn + 1];
                int which = gn >> 10, hh = (gn & 1023) >> 6, dd = gn & 63;
                int b2 = gm >> 9, n2 = gm & 511;
                size_t di = ((((size_t)b2 * HH + hh) * NN) + n2) * HD + dd;
                __nv_bfloat16* dh = which == 0 ? g_q_h : g_k_h;
                __nv_bfloat16* dl = which == 0 ? g_q_l : g_k_l;
                __nv_bfloat16 h0 = __float2bfloat16(v0);
                __nv_bfloat16 h1 = __float2bfloat16(v1);
                union { unsigned short u[2]; uint32_t d; } Hh, Ll;
                Hh.u[0] = bfbits(h0); Hh.u[1] = bfbits(h1);
                Ll.u[0] = bfbits(__float2bfloat16(v0 - __bfloat162float(h0)));
                Ll.u[1] = bfbits(__float2bfloat16(v1 - __bfloat162float(h1)));
                *(uint32_t*)(dh + di) = Hh.d;
                *(uint32_t*)(dl + di) = Ll.d;
            }
        }
    }
}

// ---------------- fp16 1-pass GEMM (A single, B single) -------------------
// MODE 2: Oh = fp16 gelu(acc+bias); MODE 4: fp32 partial; MODE 5: V scatter
#define XSA 0
#define XSB 20480
#define STGX 30720
#define SMEMX (3*STGX)

__global__ void __launch_bounds__(512, 1)
k_hf16x1(const unsigned short* __restrict__ Ap, const unsigned short* __restrict__ Wp,
         const float* __restrict__ bias,
         float* __restrict__ C0, float* __restrict__ C1,
         unsigned short* __restrict__ Oh,
         int Kfull, int Ksub, int N, int MODE) {
    extern __shared__ char smem[];
    uint32_t sb = smem_u32(smem);
    const int tid = threadIdx.x, lane = tid & 31, wid = tid >> 5;
    const int warp_m = wid & 3, warp_n = wid >> 2;
    const int row0 = blockIdx.y * 256, col0 = blockIdx.x * 128;
    const int z = blockIdx.z;
    const int Kb = Kfull * 2;
    const size_t kst = (size_t)z * Ksub * 2;

    const char* gA = (const char*)Ap + (size_t)row0 * Kb + kst;
    const char* gB = (const char*)Wp + (size_t)col0 * Kb + kst;

    const int arow = tid >> 2, acol = (tid & 3) * 16;
    const uint32_t aOff = (uint32_t)((warp_m * 64 + (lane & 15)) * 80
                                     + ((lane >> 4) & 1) * 16);
    const uint32_t bOff = (uint32_t)((warp_n * 32 + (lane & 7) + ((lane >> 4) & 1) * 8) * 80
                                     + ((lane >> 3) & 1) * 16);

    float acc[4][4][4] = {};
    const int stages = Ksub >> 5;

    #define ISSUEX(s) do { \
        uint32_t dbase = sb + ((s) % 3) * STGX; \
        size_t kbyte = (size_t)(s) * 64; \
        CP16(dbase + XSA + arow * 80 + acol,          gA + (size_t)arow * Kb + kbyte + acol); \
        CP16(dbase + XSA + (arow + 128) * 80 + acol,  gA + (size_t)(arow + 128) * Kb + kbyte + acol); \
        CP16(dbase + XSB + arow * 80 + acol,          gB + (size_t)arow * Kb + kbyte + acol); \
    } while (0)

    ISSUEX(0); CP_COMMIT();
    if (stages > 1) ISSUEX(1);
    CP_COMMIT();

    for (int s = 0; s < stages; s++) {
        CP_WAIT1();
        __syncthreads();
        if (s + 2 < stages) ISSUEX(s + 2);
        CP_COMMIT();

        uint32_t base = sb + (s % 3) * STGX;
        #pragma unroll
        for (int ko = 0; ko < 2; ko++) {
            uint32_t koff = ko * 32;
            uint32_t Af[4][4], Bf[2][4];
            #pragma unroll
            for (int fm = 0; fm < 4; fm++)
                LDSM4(Af[fm], base + XSA + aOff + fm * 16 * 80 + koff);
            #pragma unroll
            for (int p = 0; p < 2; p++)
                LDSM4(Bf[p], base + XSB + bOff + p * 16 * 80 + koff);
            #pragma unroll
            for (int fm = 0; fm < 4; fm++)
                #pragma unroll
                for (int fn = 0; fn < 4; fn++)
                    MMAF16(acc[fm][fn], Af[fm], &Bf[fn >> 1][(fn & 1) * 2]);
        }
        __syncthreads();
    }

    const int mrow = lane >> 2, ncol = (lane & 3) * 2;
    if (MODE == 4) {
        float* C = z == 0 ? C0 : C1;
        #pragma unroll
        for (int fm = 0; fm < 4; fm++)
            #pragma unroll
            for (int fn = 0; fn < 4; fn++)
                #pragma unroll
                for (int half = 0; half < 2; half++) {
                    int gm = row0 + warp_m * 64 + fm * 16 + mrow + half * 8;
                    int gn = col0 + warp_n * 32 + fn * 8 + ncol;
                    float2 o;
                    o.x = acc[fm][fn][half * 2 + 0];
                    o.y = acc[fm][fn][half * 2 + 1];
                    *(float2*)&C[(size_t)gm * N + gn] = o;
                }
    } else if (MODE == 5) {   // V scatter: per-head fp16 single
        #pragma unroll
        for (int fm = 0; fm < 4; fm++)
            #pragma unroll
            for (int fn = 0; fn < 4; fn++)
                #pragma unroll
                for (int half = 0; half < 2; half++) {
                    int gm = row0 + warp_m * 64 + fm * 16 + mrow + half * 8;
                    int gn = col0 + warp_n * 32 + fn * 8 + ncol;
                    float v0 = acc[fm][fn][half * 2 + 0] + bias[gn];
                    float v1 = acc[fm][fn][half * 2 + 1] + bias[gn + 1];
                    int hh = gn >> 6, dd = gn & 63;
                    int b2 = gm >> 9, n2 = gm & 511;
                    size_t di = ((((size_t)b2 * HH + hh) * NN) + n2) * HD + dd;
                    *(uint32_t*)(g_v_f + di) = packhf(v0, v1);
                }
    } else {  // MODE 2: gelu -> fp16 single
        #pragma unroll
        for (int fm = 0; fm < 4; fm++)
            #pragma unroll
            for (int fn = 0; fn < 4; fn++)
                #pragma unroll
                for (int half = 0; half < 2; half++) {
                    int gm = row0 + warp_m * 64 + fm * 16 + mrow + half * 8;
                    int gn = col0 + warp_n * 32 + fn * 8 + ncol;
                    float v0 = acc[fm][fn][half * 2 + 0] + bias[gn];
                    float v1 = acc[fm][fn][half * 2 + 1] + bias[gn + 1];
                    v0 = 0.5f * v0 * (1.f + erff(v0 * 0.70710678118654752f));
                    v1 = 0.5f * v1 * (1.f + erff(v1 * 0.70710678118654752f));
                    *(uint32_t*)(Oh + (size_t)gm * N + gn) = packhf(v0, v1);
                }
    }
}

// ---------------- split-K2 combiner (final output) ----------------
__global__ void k_comb2(const float4* __restrict__ p0, const float4* __restrict__ p1,
                        const float* __restrict__ bias, const float4* __restrict__ resid,
                        int gate_off, float4* __restrict__ out) {
    int i = blockIdx.x * blockDim.x + threadIdx.x;
    int gm = i >> 8;
    int gn4 = (i & 255) * 4;
    int b = gm >> 9;
    float4 a = p0[i], c = p1[i], r = resid[i];
    const float* gate = g_mod + b * MODD + gate_off + gn4;
    const float* bs = bias + gn4;
    float4 o;
    o.x = r.x + gate[0] * (a.x + c.x + bs[0]);
    o.y = r.y + gate[1] * (a.y + c.y + bs[1]);
    o.z = r.z + gate[2] * (a.z + c.z + bs[2]);
    o.w = r.w + gate[3] * (a.w + c.w + bs[3]);
    out[i] = o;
}

// ---------------- rel-pos bias MLP with HMMA layer 2 ----------------
#define KB_W2  0
#define KB_H   2304
#define KB_SMEM (2304 + 512*144)
__global__ void __launch_bounds__(256)
k_bias2(const float* __restrict__ rp,
        const float* __restrict__ w1, const float* __restrict__ b1,
        const float* __restrict__ w2, const float* __restrict__ b2) {
    extern __shared__ char smem[];
    uint32_t sbm = smem_u32(smem);
    __shared__ float sw1[128], sb1[64], sb2[16];
    int tid = threadIdx.x, lane = tid & 31, wid = tid >> 5;
    if (tid < 128) sw1[tid] = w1[tid];
    if (tid < 64)  sb1[tid] = b1[tid];
    if (tid < 16)  sb2[tid] = b2[tid];
    for (int i = tid; i < 1024; i += 256) {
        int hh = i >> 6, u = i & 63;
        *(unsigned short*)(smem + KB_W2 + hh * 144 + u * 2) = hfbits(__float2half_rn(w2[i]));
    }
    __syncthreads();
    int bi = blockIdx.x;
    int b = bi >> 9, i = bi & 511;
    #pragma unroll
    for (int jj = 0; jj < 2; jj++) {
        int j = tid + jj * 256;
        float2 r = ((const float2*)rp)[(size_t)bi * NN + j];
        char* hrow = smem + KB_H + j * 144;
        #pragma unroll 4
        for (int u = 0; u < 64; u += 2) {
            float h0 = fmaxf(0.f, fmaf(sw1[2 * u],     r.x, fmaf(sw1[2 * u + 1], r.y, sb1[u])));
            float h1 = fmaxf(0.f, fmaf(sw1[2 * u + 2], r.x, fmaf(sw1[2 * u + 3], r.y, sb1[u + 1])));
            *(uint32_t*)(hrow + u * 2) = packhf(h0, h1);
        }
    }
    __syncthreads();
    const uint32_t aOff = sbm + KB_H + (uint32_t)((wid * 64 + (lane & 15)) * 144
                                                  + ((lane >> 4) & 1) * 16);
    const uint32_t bAddr = sbm + KB_W2 + (uint32_t)(((lane & 7) + ((lane >> 4) & 1) * 8) * 144
                                                    + ((lane >> 3) & 1) * 16);
    float acc[4][2][4] = {};
    #pragma unroll
    for (int ks = 0; ks < 4; ks++) {
        uint32_t kc = ks * 32;
        uint32_t Bf[4];
        LDSM4(Bf, bAddr + kc);
        #pragma unroll
        for (int fm = 0; fm < 4; fm++) {
            uint32_t Af[4];
            LDSM4(Af, aOff + fm * 16 * 144 + kc);
            MMAF16(acc[fm][0], Af, &Bf[0]);
            MMAF16(acc[fm][1], Af, &Bf[2]);
        }
    }
    const int mrow = lane >> 2, ncol = (lane & 3) * 2;
    #pragma unroll
    for (int fm = 0; fm < 4; fm++)
        #pragma unroll
        for (int fn = 0; fn < 2; fn++)
            #pragma unroll
            for (int half = 0; half < 2; half++) {
                int j = wid * 64 + fm * 16 + mrow + half * 8;
                int hh = fn * 8 + ncol;
                float v0 = acc[fm][fn][half * 2 + 0] + sb2[hh];
                float v1 = acc[fm][fn][half * 2 + 1] + sb2[hh + 1];
                g_biasb[(((size_t)(b * HH + hh)     * NN) + i) * NN + j] = __float2bfloat16(v0);
                g_biasb[(((size_t)(b * HH + hh + 1) * NN) + i) * NN + j] = __float2bfloat16(v1);
            }
}

// ---------------- fused flash attention (online softmax, 128 rows/CTA) ----
// scores bf16x3 (Q,K hi/lo); PV fp16 1-pass; double-buffered KV; 256 thr
#define FA4_SQH 0
#define FA4_SQL 18432
#define FA4_BUF 36864
#define FA4_KH 0
#define FA4_KL 18432
#define FA4_VF 36864
#define FA4_SB 55296
#define FA4_KBUF 90112
#define FA4_SM (36864 + 2*90112)
#define FA4_SMEM (FA4_SM + 2048)

__device__ __forceinline__ void fa_issue(uint32_t sb, int bh, int i0,
                                         int j0, uint32_t bufbase, int tid) {
    const __nv_bfloat16* kh = g_k_h + ((size_t)bh * NN + j0) * HD;
    const __nv_bfloat16* kl = g_k_l + ((size_t)bh * NN + j0) * HD;
    const unsigned short* vf = g_v_f + ((size_t)bh * NN + j0) * HD;
    for (int idx = tid; idx < 1024; idx += 256) {
        int row = idx >> 3, c = idx & 7;
        uint32_t so = bufbase + row * 144 + c * 16;
        size_t go = (size_t)row * HD;
        CP16(sb + FA4_KH + so, (const char*)(kh + go) + c * 16);
        CP16(sb + FA4_KL + so, (const char*)(kl + go) + c * 16);
        CP16(sb + FA4_VF + so, (const char*)(vf + go) + c * 16);
    }
    const __nv_bfloat16* bsrc = g_biasb + ((size_t)bh * NN + i0) * NN + j0;
    for (int idx = tid; idx < 2048; idx += 256) {
        int row = idx >> 4, c = idx & 15;
        CP16(sb + FA4_SB + bufbase + row * 272 + c * 16,
             (const char*)(bsrc + (size_t)row * NN) + c * 16);
    }
}

__global__ void __launch_bounds__(256, 1)
k_fa(const int* __restrict__ amask) {
    extern __shared__ char smem[];
    uint32_t sb = smem_u32(smem);
    const int tid = threadIdx.x, lane = tid & 31, wid = tid >> 5;  // 8 warps, 16 rows each
    const int bh = blockIdx.y, b = bh >> 4, h = bh & 15;
    const int i0 = blockIdx.x * 128;

    {
        const __nv_bfloat16* qh = g_q_h + ((size_t)bh * NN + i0) * HD;
        const __nv_bfloat16* ql = g_q_l + ((size_t)bh * NN + i0) * HD;
        for (int idx = tid; idx < 1024; idx += 256) {
            int row = idx >> 3, c = idx & 7;
            CP16(sb + FA4_SQH + row * 144 + c * 16, (const char*)(qh + (size_t)row * HD) + c * 16);
            CP16(sb + FA4_SQL + row * 144 + c * 16, (const char*)(ql + (size_t)row * HD) + c * 16);
        }
        float* smask = (float*)(smem + FA4_SM);
        for (int j = tid; j < 512; j += 256)
            smask[j] = amask[b * NN + j] ? 0.f : -1e30f;
    }
    fa_issue(sb, bh, i0, 0, FA4_BUF, tid);
    CP_COMMIT();
    fa_issue(sb, bh, i0, 128, FA4_BUF + FA4_KBUF, tid);
    CP_COMMIT();

    const uint32_t aRow = (uint32_t)((wid * 16 + (lane & 15)) * 144 + ((lane >> 4) & 1) * 16);
    const uint32_t bRow = (uint32_t)(((lane & 7) + ((lane >> 4) & 1) * 8) * 144
                                     + ((lane >> 3) & 1) * 16);
    const uint32_t vRow = (uint32_t)(((lane & 7) + ((lane >> 3) & 1) * 8) * 144
                                     + ((lane >> 4) & 1) * 16);

    float oacc[8][4] = {};
    float rsum0 = 0.f, rsum1 = 0.f;
    float m0 = -1e30f, m1 = -1e30f;
    const float* smask = (const float*)(smem + FA4_SM);

    for (int j = 0; j < 4; j++) {
        const int j0 = j * 128;
        if (j < 3) CP_WAIT1(); else CP_WAIT0();
        __syncthreads();

        uint32_t kb0 = FA4_BUF + (j & 1) * FA4_KBUF;

        // ---- scores (bf16x3) ----
        float sacc[16][4] = {};
        #pragma unroll
        for (int ks = 0; ks < 4; ks++) {
            uint32_t kb = ks * 32;
            uint32_t qhf[4], qlf[4];
            LDSM4(qhf, sb + FA4_SQH + aRow + kb);
            LDSM4(qlf, sb + FA4_SQL + aRow + kb);
            #pragma unroll
            for (int pr = 0; pr < 8; pr++) {
                uint32_t kaddr = kb0 + bRow + pr * 16 * 144 + kb;
                uint32_t khf[4], klf[4];
                LDSM4(khf, sb + FA4_KH + kaddr);
                MMA16816(sacc[2 * pr + 0], qhf, &khf[0]);
                MMA16816(sacc[2 * pr + 1], qhf, &khf[2]);
                MMA16816(sacc[2 * pr + 0], qlf, &khf[0]);
                MMA16816(sacc[2 * pr + 1], qlf, &khf[2]);
                LDSM4(klf, sb + FA4_KL + kaddr);
                MMA16816(sacc[2 * pr + 0], qhf, &klf[0]);
                MMA16816(sacc[2 * pr + 1], qhf, &klf[2]);
            }
        }

        // ---- logits + online max ----
        const int rl0 = wid * 16 + (lane >> 2);
        const int cbase = (lane & 3) * 2;
        const char* bsb = smem + FA4_SB + kb0;
        float tm0 = -1e30f, tm1 = -1e30f;
        #pragma unroll
        for (int nt = 0; nt < 16; nt++) {
            int cl = nt * 8 + cbase;
            uint32_t b0raw = *(const uint32_t*)(bsb + (rl0)     * 272 + cl * 2);
            uint32_t b1raw = *(const uint32_t*)(bsb + (rl0 + 8) * 272 + cl * 2);
            __nv_bfloat162 bb0 = *reinterpret_cast<__nv_bfloat162*>(&b0raw);
            __nv_bfloat162 bb1 = *reinterpret_cast<__nv_bfloat162*>(&b1raw);
            float msk0 = smask[j0 + cl], msk1 = smask[j0 + cl + 1];
            sacc[nt][0] = sacc[nt][0] * 0.125f + __bfloat162float(bb0.x) + msk0;
            sacc[nt][1] = sacc[nt][1] * 0.125f + __bfloat162float(bb0.y) + msk1;
            sacc[nt][2] = sacc[nt][2] * 0.125f + __bfloat162float(bb1.x) + msk0;
            sacc[nt][3] = sacc[nt][3] * 0.125f + __bfloat162float(bb1.y) + msk1;
            tm0 = fmaxf(tm0, fmaxf(sacc[nt][0], sacc[nt][1]));
            tm1 = fmaxf(tm1, fmaxf(sacc[nt][2], sacc[nt][3]));
        }
        tm0 = fmaxf(tm0, __shfl_xor_sync(0xffffffffu, tm0, 1));
        tm0 = fmaxf(tm0, __shfl_xor_sync(0xffffffffu, tm0, 2));
        tm1 = fmaxf(tm1, __shfl_xor_sync(0xffffffffu, tm1, 1));
        tm1 = fmaxf(tm1, __shfl_xor_sync(0xffffffffu, tm1, 2));
        float nm0 = fmaxf(m0, tm0), nm1 = fmaxf(m1, tm1);
        float sc0 = __expf(m0 - nm0), sc1 = __expf(m1 - nm1);
        rsum0 *= sc0; rsum1 *= sc1;
        #pragma unroll
        for (int g = 0; g < 8; g++) {
            oacc[g][0] *= sc0; oacc[g][1] *= sc0;
            oacc[g][2] *= sc1; oacc[g][3] *= sc1;
        }
        m0 = nm0; m1 = nm1;

        // ---- exp(s - m) -> P fp16 fragments ----
        uint32_t ph[16][2];
        #pragma unroll
        for (int nt = 0; nt < 16; nt++) {
            float e0 = __expf(sacc[nt][0] - nm0);
            float e1 = __expf(sacc[nt][1] - nm0);
            float e2 = __expf(sacc[nt][2] - nm1);
            float e3 = __expf(sacc[nt][3] - nm1);
            rsum0 += e0 + e1; rsum1 += e2 + e3;
            ph[nt][0] = packhf(e0, e1);
            ph[nt][1] = packhf(e2, e3);
        }

        // ---- PV (fp16 1-pass) ----
        #pragma unroll
        for (int kk = 0; kk < 8; kk++) {
            uint32_t pa[4] = {ph[2*kk][0], ph[2*kk][1], ph[2*kk+1][0], ph[2*kk+1][1]};
            #pragma unroll
            for (int g = 0; g < 4; g++) {
                uint32_t vaddr = kb0 + vRow + kk * 16 * 144 + g * 32;
                uint32_t vf[4];
                LDSM4T(vf, sb + FA4_VF + vaddr);
                MMAF16(oacc[2 * g + 0], pa, &vf[0]);
                MMAF16(oacc[2 * g + 1], pa, &vf[2]);
            }
        }
        __syncthreads();
        if (j + 2 < 4)
            fa_issue(sb, bh, i0, (j + 2) * 128, FA4_BUF + (j & 1) * FA4_KBUF, tid);
        CP_COMMIT();
    }

    rsum0 += __shfl_xor_sync(0xffffffffu, rsum0, 1);
    rsum0 += __shfl_xor_sync(0xffffffffu, rsum0, 2);
    rsum1 += __shfl_xor_sync(0xffffffffu, rsum1, 1);
    rsum1 += __shfl_xor_sync(0xffffffffu, rsum1, 2);
    float inv0 = 1.f / rsum0, inv1 = 1.f / rsum1;
    const int r0 = i0 + wid * 16 + (lane >> 2);
    #pragma unroll
    for (int nt = 0; nt < 8; nt++) {
        int c = nt * 8 + (lane & 3) * 2;
        #pragma unroll
        for (int half = 0; half < 2; half++) {
            int gr = r0 + half * 8;
            float inv = half ? inv1 : inv0;
            float v0 = oacc[nt][half * 2 + 0] * inv;
            float v1 = oacc[nt][half * 2 + 1] * inv;
            size_t di = (size_t)(b * NN + gr) * DD + h * HD + c;
            *(uint32_t*)(g_ao_h + di) = packhf(v0, v1);
        }
    }
}

// ---------------- launch ----------------
extern "C" void kernel_launch(void* const* d_in, const int* in_sizes, int n_in,
                              void* d_out, int out_size) {
    (void)in_sizes; (void)n_in; (void)out_size;
    const float* x      = (const float*)d_in[0];
    const float* t_emb  = (const float*)d_in[1];
    const float* rp     = (const float*)d_in[2];
    const int*   amask  = (const int*)  d_in[3];
    const float* w_ada  = (const float*)d_in[4];
    const float* b_ada  = (const float*)d_in[5];
    const float* g1     = (const float*)d_in[6];
    const float* beta1  = (const float*)d_in[7];
    const float* g2     = (const float*)d_in[8];
    const float* beta2  = (const float*)d_in[9];
    const float* w_qkv  = (const float*)d_in[10];
    const float* b_qkv  = (const float*)d_in[11];
    const float* w_proj = (const float*)d_in[12];
    const float* b_proj = (const float*)d_in[13];
    const float* w_rp1  = (const float*)d_in[14];
    const float* b_rp1  = (const float*)d_in[15];
    const float* w_rp2  = (const float*)d_in[16];
    const float* b_rp2  = (const float*)d_in[17];
    const float* w_fc1  = (const float*)d_in[18];
    const float* b_fc1  = (const float*)d_in[19];
    const float* w_fc2  = (const float*)d_in[20];
    const float* b_fc2  = (const float*)d_in[21];
    float* out = (float*)d_out;

    cudaFuncSetAttribute(k_hmma2,  cudaFuncAttributeMaxDynamicSharedMemorySize, SMEM2);
    cudaFuncSetAttribute(k_hf16x1, cudaFuncAttributeMaxDynamicSharedMemorySize, SMEMX);
    cudaFuncSetAttribute(k_fa,     cudaFuncAttributeMaxDynamicSharedMemorySize, FA4_SMEM);
    cudaFuncSetAttribute(k_bias2,  cudaFuncAttributeMaxDynamicSharedMemorySize, KB_SMEM);

    void *p;
    unsigned short *xn_h, *xn_l, *xn_f, *ao_h, *hbuf, *wvf, *wpf, *w1f, *w2f;
    __nv_bfloat16 *wqk_h, *wqk_l;
    float *p_x1, *pt0, *pt1;
    cudaGetSymbolAddress(&p, g_xn_h);  xn_h = (unsigned short*)p;
    cudaGetSymbolAddress(&p, g_xn_l);  xn_l = (unsigned short*)p;
    cudaGetSymbolAddress(&p, g_xn_f);  xn_f = (unsigned short*)p;
    cudaGetSymbolAddress(&p, g_ao_h);  ao_h = (unsigned short*)p;
    cudaGetSymbolAddress(&p, g_hbuf);  hbuf = (unsigned short*)p;
    cudaGetSymbolAddress(&p, g_wqk_h); wqk_h = (__nv_bfloat16*)p;
    cudaGetSymbolAddress(&p, g_wqk_l); wqk_l = (__nv_bfloat16*)p;
    cudaGetSymbolAddress(&p, g_wv_f);  wvf  = (unsigned short*)p;
    cudaGetSymbolAddress(&p, g_wp_f);  wpf  = (unsigned short*)p;
    cudaGetSymbolAddress(&p, g_w1_f);  w1f  = (unsigned short*)p;
    cudaGetSymbolAddress(&p, g_w2_f);  w2f  = (unsigned short*)p;
    cudaGetSymbolAddress(&p, g_x1);    p_x1 = (float*)p;
    cudaGetSymbolAddress(&p, g_part0); pt0  = (float*)p;
    cudaGetSymbolAddress(&p, g_part1); pt1  = (float*)p;

    // side stream (created per call; harness calls only for correctness+capture)
    cudaStream_t s1;
    cudaEvent_t e0, e1, e2;
    cudaStreamCreateWithFlags(&s1, cudaStreamNonBlocking);
    cudaEventCreateWithFlags(&e0, cudaEventDisableTiming);
    cudaEventCreateWithFlags(&e1, cudaEventDisableTiming);
    cudaEventCreateWithFlags(&e2, cudaEventDisableTiming);

    // fork: bias MLP + non-QK weight conversion on side stream
    cudaEventRecord(e0, 0);
    cudaStreamWaitEvent(s1, e0, 0);
    k_bias2<<<BB * NN, 256, KB_SMEM, s1>>>(rp, w_rp1, b_rp1, w_rp2, b_rp2);
    k_cvtrest<<<2048, 256, 0, s1>>>((const float4*)w_qkv, (const float4*)w_proj,
                                    (const float4*)w_fc1, (const float4*)w_fc2);

    // main stream: modulation chain + QK weight conversion
    k_silu<<<16, 256>>>(t_emb);
    k_mod<<<(BB * MODD * 32 + 255) / 256, 256>>>(w_ada, b_ada);
    k_ln_mod<<<TOK, 256>>>(x, g1, beta1, 0, DD, xn_h, xn_l, xn_f);
    cudaEventRecord(e2, 0);   // xn ready (V GEMM needs this + wv from s1)
    k_cvtqk<<<2048, 256>>>((const float4*)w_qkv);

    // Q,K projection (bf16x3, N=2048, 128 CTAs) on main stream
    k_hmma2<<<dim3(2*DD/128, TOK/256, 1), 512, SMEM2>>>(
        (const __nv_bfloat16*)xn_h, (const __nv_bfloat16*)xn_l, wqk_h, wqk_l,
        b_qkv, DD, 2*DD);

    // V projection on side stream (overlaps QK GEMM)
    cudaStreamWaitEvent(s1, e2, 0);
    k_hf16x1<<<dim3(DD/128, TOK/256, 1), 512, SMEMX, s1>>>(
        xn_f, wvf, b_qkv + 2*DD, nullptr, nullptr, nullptr, DD, DD, DD, 5);
    cudaEventRecord(e1, s1);

    // join: flash attention needs QK (main) + V + bias (s1)
    cudaStreamWaitEvent(0, e1, 0);
    k_fa<<<dim3(4, BB * HH), 256, FA4_SMEM>>>(amask);

    // proj (fp16 1-pass, split-K 2, 128 CTAs) + fused combine+LN2
    k_hf16x1<<<dim3(DD/128, TOK/256, 2), 512, SMEMX>>>(
        ao_h, wpf, nullptr, pt0, pt1, nullptr, DD, DD/2, DD, 4);
    k_comb_ln<<<TOK, 256>>>((const float4*)pt0, (const float4*)pt1,
                            b_proj, (const float4*)x, 2*DD,
                            g2, beta2, 3*DD, 4*DD,
                            (float4*)p_x1, xn_h);

    // fc1 gelu (fp16 1-pass)
    k_hf16x1<<<dim3(HID/128, TOK/256, 1), 512, SMEMX>>>(
        xn_h, w1f, b_fc1, nullptr, nullptr, hbuf, DD, DD, HID, 2);

    // fc2 (fp16 1-pass, split-K 2, 128 CTAs) + final combine
    k_hf16x1<<<dim3(DD/128, TOK/256, 2), 512, SMEMX>>>(
        hbuf, w2f, nullptr, pt0, pt1, nullptr, HID, HID/2, DD, 4);
    k_comb2<<<TOK*DD/4/256, 256>>>((const float4*)pt0, (const float4*)pt1,
                                   b_fc2, (const float4*)p_x1, 5*DD, (float4*)out);
}

// round 16
// speedup vs baseline: 1.5047x; 1.5047x over previous
#include <cuda_runtime.h>
#include <cuda_bf16.h>
#include <cuda_fp16.h>
#include <math.h>
#include <stdint.h>

// ---------------- problem constants ----------------
#define BB   4
#define NN   512
#define DD   1024
#define HH   16
#define HD   64
#define HID  4096
#define TOK  (BB*NN)      // 2048
#define MODD (6*DD)       // 6144

// ---------------- scratch (static device globals) ----------------
__device__ float g_mod[BB*MODD];
__device__ float g_silu[BB*DD];
__device__ unsigned short g_xn_h[TOK*DD], g_xn_l[TOK*DD];  // bf16 h/l (ln1) or fp16 (ln2 in h)
__device__ unsigned short g_xn_f[TOK*DD];                  // fp16 single (ln1, for V)
__device__ __nv_bfloat16 g_q_h[TOK*DD], g_q_l[TOK*DD];
__device__ __nv_bfloat16 g_k_h[TOK*DD], g_k_l[TOK*DD];
__device__ unsigned short g_v_f[TOK*DD];                   // fp16 single
__device__ __nv_bfloat16 g_biasb[(size_t)BB*HH*NN*NN];     // 32 MB bf16
__device__ unsigned short g_ao_h[TOK*DD];                  // fp16 single
__device__ float g_x1[TOK*DD];
__device__ float g_part0[TOK*DD], g_part1[TOK*DD];
__device__ unsigned short g_hbuf[(size_t)TOK*HID];         // fp16 single
__device__ __nv_bfloat16 g_wqk_h[2*DD*DD], g_wqk_l[2*DD*DD];
__device__ unsigned short g_wv_f[DD*DD];
__device__ unsigned short g_wp_f[DD*DD];
__device__ unsigned short g_w1_f[(size_t)HID*DD];
__device__ unsigned short g_w2_f[(size_t)DD*HID];

// ---------------- helpers ----------------
__device__ __forceinline__ uint32_t smem_u32(const void* p) {
    uint32_t a;
    asm("{ .reg .u64 t; cvta.to.shared.u64 t, %1; cvt.u32.u64 %0, t; }" : "=r"(a) : "l"(p));
    return a;
}
__device__ __forceinline__ unsigned short bfbits(__nv_bfloat16 v) {
    return *reinterpret_cast<unsigned short*>(&v);
}
__device__ __forceinline__ unsigned short hfbits(__half v) {
    return *reinterpret_cast<unsigned short*>(&v);
}
__device__ __forceinline__ uint32_t packhf(float a, float b) {
    return (uint32_t)hfbits(__float2half_rn(a)) | ((uint32_t)hfbits(__float2half_rn(b)) << 16);
}

#define LDSM4(r, addr) \
    asm volatile("ldmatrix.sync.aligned.m8n8.x4.shared.b16 {%0,%1,%2,%3}, [%4];" \
        : "=r"((r)[0]), "=r"((r)[1]), "=r"((r)[2]), "=r"((r)[3]) : "r"(addr))
#define LDSM4T(r, addr) \
    asm volatile("ldmatrix.sync.aligned.m8n8.x4.trans.shared.b16 {%0,%1,%2,%3}, [%4];" \
        : "=r"((r)[0]), "=r"((r)[1]), "=r"((r)[2]), "=r"((r)[3]) : "r"(addr))

#define MMA16816(d, a, b) \
    asm volatile("mma.sync.aligned.m16n8k16.row.col.f32.bf16.bf16.f32 " \
        "{%0,%1,%2,%3}, {%4,%5,%6,%7}, {%8,%9}, {%0,%1,%2,%3};" \
        : "+f"((d)[0]), "+f"((d)[1]), "+f"((d)[2]), "+f"((d)[3]) \
        : "r"((a)[0]), "r"((a)[1]), "r"((a)[2]), "r"((a)[3]), \
          "r"((b)[0]), "r"((b)[1]))
#define MMAF16(d, a, b) \
    asm volatile("mma.sync.aligned.m16n8k16.row.col.f32.f16.f16.f32 " \
        "{%0,%1,%2,%3}, {%4,%5,%6,%7}, {%8,%9}, {%0,%1,%2,%3};" \
        : "+f"((d)[0]), "+f"((d)[1]), "+f"((d)[2]), "+f"((d)[3]) \
        : "r"((a)[0]), "r"((a)[1]), "r"((a)[2]), "r"((a)[3]), \
          "r"((b)[0]), "r"((b)[1]))

#define CP16(dst, src) \
    asm volatile("cp.async.cg.shared.global [%0], [%1], 16;" :: "r"(dst), "l"(src) : "memory")
#define CP_COMMIT() asm volatile("cp.async.commit_group;" ::: "memory")
#define CP_WAIT1()  asm volatile("cp.async.wait_group 1;" ::: "memory")
#define CP_WAIT0()  asm volatile("cp.async.wait_group 0;" ::: "memory")

// ---------------- merged weight conversion ----------------
#define QK_F4 (2*DD*DD/4)
#define V_F4  (DD*DD/4)
#define WP_F4 (DD*DD/4)
#define W1_F4 ((size_t)HID*DD/4)
#define CVT_TOTAL (QK_F4 + V_F4 + WP_F4 + 2*W1_F4)
__global__ void k_cvtall(const float4* __restrict__ wqkv, const float4* __restrict__ wp,
                         const float4* __restrict__ w1, const float4* __restrict__ w2) {
    for (size_t i = blockIdx.x * blockDim.x + threadIdx.x; i < CVT_TOTAL;
         i += (size_t)gridDim.x * blockDim.x) {
        if (i < QK_F4) {
            float4 v = wqkv[i];
            float vv[4] = {v.x, v.y, v.z, v.w};
            union { unsigned short u[4]; uint2 d; } H, L;
            #pragma unroll
            for (int j = 0; j < 4; j++) {
                __nv_bfloat16 hb = __float2bfloat16(vv[j]);
                H.u[j] = bfbits(hb);
                L.u[j] = bfbits(__float2bfloat16(vv[j] - __bfloat162float(hb)));
            }
            ((uint2*)g_wqk_h)[i] = H.d;
            ((uint2*)g_wqk_l)[i] = L.d;
        } else {
            const float4* src;
            uint2* dst;
            size_t j;
            if (i < QK_F4 + V_F4) {
                j = i - QK_F4; src = wqkv + QK_F4 + j; dst = (uint2*)g_wv_f;
            } else if (i < QK_F4 + V_F4 + WP_F4) {
                j = i - QK_F4 - V_F4; src = wp + j; dst = (uint2*)g_wp_f;
            } else if (i < QK_F4 + V_F4 + WP_F4 + W1_F4) {
                j = i - QK_F4 - V_F4 - WP_F4; src = w1 + j; dst = (uint2*)g_w1_f;
            } else {
                j = i - QK_F4 - V_F4 - WP_F4 - W1_F4; src = w2 + j; dst = (uint2*)g_w2_f;
            }
            float4 v = *src;
            union { unsigned short u[4]; uint2 d; } H;
            H.u[0] = hfbits(__float2half_rn(v.x));
            H.u[1] = hfbits(__float2half_rn(v.y));
            H.u[2] = hfbits(__float2half_rn(v.z));
            H.u[3] = hfbits(__float2half_rn(v.w));
            dst[j] = H.d;
        }
    }
}

// ---------------- silu precompute + adaLN modulation ----------------
__global__ void k_silu(const float* __restrict__ t_emb) {
    int i = blockIdx.x * blockDim.x + threadIdx.x;
    if (i < BB * DD) {
        float t = t_emb[i];
        g_silu[i] = t / (1.f + __expf(-t));
    }
}
__global__ void k_mod(const float* __restrict__ w_ada,
                      const float* __restrict__ b_ada) {
    int warp = (blockIdx.x * blockDim.x + threadIdx.x) >> 5;
    int lane = threadIdx.x & 31;
    if (warp >= BB * MODD) return;
    int b = warp / MODD, o = warp % MODD;
    const float* te = g_silu + b * DD;
    const float* w  = w_ada + (size_t)o * DD;
    float acc = 0.f;
    #pragma unroll 8
    for (int k = lane; k < DD; k += 32)
        acc = fmaf(te[k], w[k], acc);
    #pragma unroll
    for (int off = 16; off; off >>= 1)
        acc += __shfl_xor_sync(0xffffffffu, acc, off);
    if (lane == 0) g_mod[b * MODD + o] = acc + b_ada[o];
}

// ---------------- LayerNorm1 + modulate -> bf16 hi/lo + fp16 ----------------
__global__ void k_ln_mod(const float* __restrict__ x,
                         const float* __restrict__ g,
                         const float* __restrict__ beta,
                         int shift_off, int scale_off,
                         unsigned short* __restrict__ oh,
                         unsigned short* __restrict__ ol,
                         unsigned short* __restrict__ of) {
    int t = blockIdx.x;
    int b = t >> 9;
    const float* xr = x + (size_t)t * DD;
    float v[4];
    float s = 0.f, ss = 0.f;
    #pragma unroll
    for (int i = 0; i < 4; i++) {
        v[i] = xr[threadIdx.x + i * 256];
        s += v[i]; ss += v[i] * v[i];
    }
    __shared__ float shs[8], shss[8];
    #pragma unroll
    for (int o = 16; o; o >>= 1) {
        s  += __shfl_xor_sync(0xffffffffu, s,  o);
        ss += __shfl_xor_sync(0xffffffffu, ss, o);
    }
    int w = threadIdx.x >> 5, l = threadIdx.x & 31;
    if (l == 0) { shs[w] = s; shss[w] = ss; }
    __syncthreads();
    if (w == 0) {
        s  = (l < 8) ? shs[l]  : 0.f;
        ss = (l < 8) ? shss[l] : 0.f;
        #pragma unroll
        for (int o = 4; o; o >>= 1) {
            s  += __shfl_xor_sync(0xffffffffu, s,  o);
            ss += __shfl_xor_sync(0xffffffffu, ss, o);
        }
        if (l == 0) { shs[0] = s; shss[0] = ss; }
    }
    __syncthreads();
    float mu  = shs[0] * (1.f / DD);
    float var = shss[0] * (1.f / DD) - mu * mu;
    float r   = rsqrtf(var + 1e-5f);
    const float* shiftp = g_mod + b * MODD + shift_off;
    const float* scalep = g_mod + b * MODD + scale_off;
    #pragma unroll
    for (int i = 0; i < 4; i++) {
        int d = threadIdx.x + i * 256;
        float xn = (v[i] - mu) * r * g[d] + beta[d];
        float o = xn * (1.f + scalep[d]) + shiftp[d];
        size_t idx = (size_t)t * DD + d;
        __nv_bfloat16 hb = __float2bfloat16(o);
        oh[idx] = bfbits(hb);
        ol[idx] = bfbits(__float2bfloat16(o - __bfloat162float(hb)));
        of[idx] = hfbits(__float2half_rn(o));
    }
}

// ---------------- fused proj-combine + LayerNorm2 -> fp16 ----------------
__global__ void k_comb_ln(const float4* __restrict__ p0, const float4* __restrict__ p1,
                          const float* __restrict__ bias, const float4* __restrict__ xin,
                          int gate_off,
                          const float* __restrict__ g, const float* __restrict__ beta,
                          int shift_off, int scale_off,
                          float4* __restrict__ x1out, unsigned short* __restrict__ oh) {
    int t = blockIdx.x, b = t >> 9, tid = threadIdx.x;
    int i4 = t * 256 + tid;
    int gn = tid * 4;
    const float* gate = g_mod + b * MODD + gate_off;
    float4 a = p0[i4], c = p1[i4], r = xin[i4];
    float4 v;
    v.x = r.x + gate[gn + 0] * (a.x + c.x + bias[gn + 0]);
    v.y = r.y + gate[gn + 1] * (a.y + c.y + bias[gn + 1]);
    v.z = r.z + gate[gn + 2] * (a.z + c.z + bias[gn + 2]);
    v.w = r.w + gate[gn + 3] * (a.w + c.w + bias[gn + 3]);
    x1out[i4] = v;
    float s  = v.x + v.y + v.z + v.w;
    float ss = v.x * v.x + v.y * v.y + v.z * v.z + v.w * v.w;
    __shared__ float shs[8], shss[8];
    #pragma unroll
    for (int o = 16; o; o >>= 1) {
        s  += __shfl_xor_sync(0xffffffffu, s,  o);
        ss += __shfl_xor_sync(0xffffffffu, ss, o);
    }
    int w = tid >> 5, l = tid & 31;
    if (l == 0) { shs[w] = s; shss[w] = ss; }
    __syncthreads();
    if (w == 0) {
        s  = (l < 8) ? shs[l]  : 0.f;
        ss = (l < 8) ? shss[l] : 0.f;
        #pragma unroll
        for (int o = 4; o; o >>= 1) {
            s  += __shfl_xor_sync(0xffffffffu, s,  o);
            ss += __shfl_xor_sync(0xffffffffu, ss, o);
        }
        if (l == 0) { shs[0] = s; shss[0] = ss; }
    }
    __syncthreads();
    float mu  = shs[0] * (1.f / DD);
    float var = shss[0] * (1.f / DD) - mu * mu;
    float rin = rsqrtf(var + 1e-5f);
    const float* shiftp = g_mod + b * MODD + shift_off;
    const float* scalep = g_mod + b * MODD + scale_off;
    float vv[4] = {v.x, v.y, v.z, v.w};
    union { unsigned short u[4]; uint2 d2; } H;
    #pragma unroll
    for (int j = 0; j < 4; j++) {
        int d = gn + j;
        float xn = (vv[j] - mu) * rin * g[d] + beta[d];
        float o = xn * (1.f + scalep[d]) + shiftp[d];
        H.u[j] = hfbits(__float2half_rn(o));
    }
    *(uint2*)(oh + (size_t)t * DD + gn) = H.d2;
}

// ---------------- HMMA bf16x3 GEMM (Q,K projection), 256x128 tile ---------
#define SA_H 0
#define SA_L 20480
#define SB_H 40960
#define SB_L 51200
#define STG2 61440
#define SMEM2 (3*STG2)

__global__ void __launch_bounds__(512, 1)
k_hmma2(const __nv_bfloat16* __restrict__ Ahp, const __nv_bfloat16* __restrict__ Alp,
        const __nv_bfloat16* __restrict__ Whp, const __nv_bfloat16* __restrict__ Wlp,
        const float* __restrict__ bias, int Kfull, int N) {
    extern __shared__ char smem[];
    uint32_t sb = smem_u32(smem);
    const int tid = threadIdx.x, lane = tid & 31, wid = tid >> 5;
    const int warp_m = wid & 3, warp_n = wid >> 2;
    const int row0 = blockIdx.y * 256, col0 = blockIdx.x * 128;
    const int Kb = Kfull * 2;

    const char* gA0 = (const char*)Ahp + (size_t)row0 * Kb;
    const char* gA1 = (const char*)Alp + (size_t)row0 * Kb;
    const char* gB0 = (const char*)Whp + (size_t)col0 * Kb;
    const char* gB1 = (const char*)Wlp + (size_t)col0 * Kb;

    const int arow = tid >> 2, acol = (tid & 3) * 16;
    const uint32_t aOff = (uint32_t)((warp_m * 64 + (lane & 15)) * 80
                                     + ((lane >> 4) & 1) * 16);
    const uint32_t bOff = (uint32_t)((warp_n * 32 + (lane & 7) + ((lane >> 4) & 1) * 8) * 80
                                     + ((lane >> 3) & 1) * 16);

    float acc[4][4][4] = {};
    const int stages = Kfull >> 5;

    #define ISSUE2(s) do { \
        uint32_t dbase = sb + ((s) % 3) * STG2; \
        size_t kbyte = (size_t)(s) * 64; \
        CP16(dbase + SA_H + arow * 80 + acol,          gA0 + (size_t)arow * Kb + kbyte + acol); \
        CP16(dbase + SA_H + (arow + 128) * 80 + acol,  gA0 + (size_t)(arow + 128) * Kb + kbyte + acol); \
        CP16(dbase + SA_L + arow * 80 + acol,          gA1 + (size_t)arow * Kb + kbyte + acol); \
        CP16(dbase + SA_L + (arow + 128) * 80 + acol,  gA1 + (size_t)(arow + 128) * Kb + kbyte + acol); \
        CP16(dbase + SB_H + arow * 80 + acol,          gB0 + (size_t)arow * Kb + kbyte + acol); \
        CP16(dbase + SB_L + arow * 80 + acol,          gB1 + (size_t)arow * Kb + kbyte + acol); \
    } while (0)

    ISSUE2(0); CP_COMMIT();
    if (stages > 1) ISSUE2(1);
    CP_COMMIT();

    for (int s = 0; s < stages; s++) {
        CP_WAIT1();
        __syncthreads();
        if (s + 2 < stages) ISSUE2(s + 2);
        CP_COMMIT();

        uint32_t base = sb + (s % 3) * STG2;
        #pragma unroll
        for (int ko = 0; ko < 2; ko++) {
            uint32_t koff = ko * 32;
            uint32_t Ahf[4][4];
            #pragma unroll
            for (int fm = 0; fm < 4; fm++)
                LDSM4(Ahf[fm], base + SA_H + aOff + fm * 16 * 80 + koff);
            uint32_t Bhf[2][4];
            #pragma unroll
            for (int p = 0; p < 2; p++)
                LDSM4(Bhf[p], base + SB_H + bOff + p * 16 * 80 + koff);
            #pragma unroll
            for (int fm = 0; fm < 4; fm++)
                #pragma unroll
                for (int fn = 0; fn < 4; fn++)
                    MMA16816(acc[fm][fn], Ahf[fm], &Bhf[fn >> 1][(fn & 1) * 2]);
            {
                uint32_t Alf[4][4];
                #pragma unroll
                for (int fm = 0; fm < 4; fm++)
                    LDSM4(Alf[fm], base + SA_L + aOff + fm * 16 * 80 + koff);
                #pragma unroll
                for (int fm = 0; fm < 4; fm++)
                    #pragma unroll
                    for (int fn = 0; fn < 4; fn++)
                        MMA16816(acc[fm][fn], Alf[fm], &Bhf[fn >> 1][(fn & 1) * 2]);
            }
            {
                uint32_t Blf[2][4];
                #pragma unroll
                for (int p = 0; p < 2; p++)
                    LDSM4(Blf[p], base + SB_L + bOff + p * 16 * 80 + koff);
                #pragma unroll
                for (int fm = 0; fm < 4; fm++)
                    #pragma unroll
                    for (int fn = 0; fn < 4; fn++)
                        MMA16816(acc[fm][fn], Ahf[fm], &Blf[fn >> 1][(fn & 1) * 2]);
            }
        }
        __syncthreads();
    }

    // epilogue: q/k scatter -> per-head bf16 hi/lo
    const int mrow = lane >> 2, ncol = (lane & 3) * 2;
    #pragma unroll
    for (int fm = 0; fm < 4; fm++) {
        #pragma unroll
        for (int fn = 0; fn < 4; fn++) {
            #pragma unroll
            for (int half = 0; half < 2; half++) {
                int gm = row0 + warp_m * 64 + fm * 16 + mrow + half * 8;
                int gn = col0 + warp_n * 32 + fn * 8 + ncol;
                float v0 = acc[fm][fn][half * 2 + 0] + bias[gn];
                float v1 = acc[fm][fn][half * 2 + 1] + bias[gn + 1];
                int which = gn >> 10, hh = (gn & 1023) >> 6, dd = gn & 63;
                int b2 = gm >> 9, n2 = gm & 511;
                size_t di = ((((size_t)b2 * HH + hh) * NN) + n2) * HD + dd;
                __nv_bfloat16* dh = which == 0 ? g_q_h : g_k_h;
                __nv_bfloat16* dl = which == 0 ? g_q_l : g_k_l;
                __nv_bfloat16 h0 = __float2bfloat16(v0);
                __nv_bfloat16 h1 = __float2bfloat16(v1);
                union { unsigned short u[2]; uint32_t d; } Hh, Ll;
                Hh.u[0] = bfbits(h0); Hh.u[1] = bfbits(h1);
                Ll.u[0] = bfbits(__float2bfloat16(v0 - __bfloat162float(h0)));
                Ll.u[1] = bfbits(__float2bfloat16(v1 - __bfloat162float(h1)));
                *(uint32_t*)(dh + di) = Hh.d;
                *(uint32_t*)(dl + di) = Ll.d;
            }
        }
    }
}

// ---------------- fp16 1-pass GEMM (A single, B single) -------------------
// MODE 2: Oh = fp16 gelu(acc+bias); MODE 4: fp32 partial; MODE 5: V scatter
#define XSA 0
#define XSB 20480
#define STGX 30720
#define SMEMX (3*STGX)

__global__ void __launch_bounds__(512, 1)
k_hf16x1(const unsigned short* __restrict__ Ap, const unsigned short* __restrict__ Wp,
         const float* __restrict__ bias,
         float* __restrict__ C0, float* __restrict__ C1,
         unsigned short* __restrict__ Oh,
         int Kfull, int Ksub, int N, int MODE) {
    extern __shared__ char smem[];
    uint32_t sb = smem_u32(smem);
    const int tid = threadIdx.x, lane = tid & 31, wid = tid >> 5;
    const int warp_m = wid & 3, warp_n = wid >> 2;
    const int row0 = blockIdx.y * 256, col0 = blockIdx.x * 128;
    const int z = blockIdx.z;
    const int Kb = Kfull * 2;
    const size_t kst = (size_t)z * Ksub * 2;

    const char* gA = (const char*)Ap + (size_t)row0 * Kb + kst;
    const char* gB = (const char*)Wp + (size_t)col0 * Kb + kst;

    const int arow = tid >> 2, acol = (tid & 3) * 16;
    const uint32_t aOff = (uint32_t)((warp_m * 64 + (lane & 15)) * 80
                                     + ((lane >> 4) & 1) * 16);
    const uint32_t bOff = (uint32_t)((warp_n * 32 + (lane & 7) + ((lane >> 4) & 1) * 8) * 80
                                     + ((lane >> 3) & 1) * 16);

    float acc[4][4][4] = {};
    const int stages = Ksub >> 5;

    #define ISSUEX(s) do { \
        uint32_t dbase = sb + ((s) % 3) * STGX; \
        size_t kbyte = (size_t)(s) * 64; \
        CP16(dbase + XSA + arow * 80 + acol,          gA + (size_t)arow * Kb + kbyte + acol); \
        CP16(dbase + XSA + (arow + 128) * 80 + acol,  gA + (size_t)(arow + 128) * Kb + kbyte + acol); \
        CP16(dbase + XSB + arow * 80 + acol,          gB + (size_t)arow * Kb + kbyte + acol); \
    } while (0)

    ISSUEX(0); CP_COMMIT();
    if (stages > 1) ISSUEX(1);
    CP_COMMIT();

    for (int s = 0; s < stages; s++) {
        CP_WAIT1();
        __syncthreads();
        if (s + 2 < stages) ISSUEX(s + 2);
        CP_COMMIT();

        uint32_t base = sb + (s % 3) * STGX;
        #pragma unroll
        for (int ko = 0; ko < 2; ko++) {
            uint32_t koff = ko * 32;
            uint32_t Af[4][4], Bf[2][4];
            #pragma unroll
            for (int fm = 0; fm < 4; fm++)
                LDSM4(Af[fm], base + XSA + aOff + fm * 16 * 80 + koff);
            #pragma unroll
            for (int p = 0; p < 2; p++)
                LDSM4(Bf[p], base + XSB + bOff + p * 16 * 80 + koff);
            #pragma unroll
            for (int fm = 0; fm < 4; fm++)
                #pragma unroll
                for (int fn = 0; fn < 4; fn++)
                    MMAF16(acc[fm][fn], Af[fm], &Bf[fn >> 1][(fn & 1) * 2]);
        }
        __syncthreads();
    }

    const int mrow = lane >> 2, ncol = (lane & 3) * 2;
    if (MODE == 4) {
        float* C = z == 0 ? C0 : C1;
        #pragma unroll
        for (int fm = 0; fm < 4; fm++)
            #pragma unroll
            for (int fn = 0; fn < 4; fn++)
                #pragma unroll
                for (int half = 0; half < 2; half++) {
                    int gm = row0 + warp_m * 64 + fm * 16 + mrow + half * 8;
                    int gn = col0 + warp_n * 32 + fn * 8 + ncol;
                    float2 o;
                    o.x = acc[fm][fn][half * 2 + 0];
                    o.y = acc[fm][fn][half * 2 + 1];
                    *(float2*)&C[(size_t)gm * N + gn] = o;
                }
    } else if (MODE == 5) {   // V scatter: per-head fp16 single
        #pragma unroll
        for (int fm = 0; fm < 4; fm++)
            #pragma unroll
            for (int fn = 0; fn < 4; fn++)
                #pragma unroll
                for (int half = 0; half < 2; half++) {
                    int gm = row0 + warp_m * 64 + fm * 16 + mrow + half * 8;
                    int gn = col0 + warp_n * 32 + fn * 8 + ncol;
                    float v0 = acc[fm][fn][half * 2 + 0] + bias[gn];
                    float v1 = acc[fm][fn][half * 2 + 1] + bias[gn + 1];
                    int hh = gn >> 6, dd = gn & 63;
                    int b2 = gm >> 9, n2 = gm & 511;
                    size_t di = ((((size_t)b2 * HH + hh) * NN) + n2) * HD + dd;
                    *(uint32_t*)(g_v_f + di) = packhf(v0, v1);
                }
    } else {  // MODE 2: gelu -> fp16 single
        #pragma unroll
        for (int fm = 0; fm < 4; fm++)
            #pragma unroll
            for (int fn = 0; fn < 4; fn++)
                #pragma unroll
                for (int half = 0; half < 2; half++) {
                    int gm = row0 + warp_m * 64 + fm * 16 + mrow + half * 8;
                    int gn = col0 + warp_n * 32 + fn * 8 + ncol;
                    float v0 = acc[fm][fn][half * 2 + 0] + bias[gn];
                    float v1 = acc[fm][fn][half * 2 + 1] + bias[gn + 1];
                    v0 = 0.5f * v0 * (1.f + erff(v0 * 0.70710678118654752f));
                    v1 = 0.5f * v1 * (1.f + erff(v1 * 0.70710678118654752f));
                    *(uint32_t*)(Oh + (size_t)gm * N + gn) = packhf(v0, v1);
                }
    }
}

// ---------------- split-K2 combiner (final output) ----------------
__global__ void k_comb2(const float4* __restrict__ p0, const float4* __restrict__ p1,
                        const float* __restrict__ bias, const float4* __restrict__ resid,
                        int gate_off, float4* __restrict__ out) {
    int i = blockIdx.x * blockDim.x + threadIdx.x;
    int gm = i >> 8;
    int gn4 = (i & 255) * 4;
    int b = gm >> 9;
    float4 a = p0[i], c = p1[i], r = resid[i];
    const float* gate = g_mod + b * MODD + gate_off + gn4;
    const float* bs = bias + gn4;
    float4 o;
    o.x = r.x + gate[0] * (a.x + c.x + bs[0]);
    o.y = r.y + gate[1] * (a.y + c.y + bs[1]);
    o.z = r.z + gate[2] * (a.z + c.z + bs[2]);
    o.w = r.w + gate[3] * (a.w + c.w + bs[3]);
    out[i] = o;
}

// ---------------- rel-pos bias MLP with HMMA layer 2 ----------------
#define KB_W2  0
#define KB_H   2304
#define KB_SMEM (2304 + 512*144)
__global__ void __launch_bounds__(256)
k_bias2(const float* __restrict__ rp,
        const float* __restrict__ w1, const float* __restrict__ b1,
        const float* __restrict__ w2, const float* __restrict__ b2) {
    extern __shared__ char smem[];
    uint32_t sbm = smem_u32(smem);
    __shared__ float sw1[128], sb1[64], sb2[16];
    int tid = threadIdx.x, lane = tid & 31, wid = tid >> 5;
    if (tid < 128) sw1[tid] = w1[tid];
    if (tid < 64)  sb1[tid] = b1[tid];
    if (tid < 16)  sb2[tid] = b2[tid];
    for (int i = tid; i < 1024; i += 256) {
        int hh = i >> 6, u = i & 63;
        *(unsigned short*)(smem + KB_W2 + hh * 144 + u * 2) = hfbits(__float2half_rn(w2[i]));
    }
    __syncthreads();
    int bi = blockIdx.x;
    int b = bi >> 9, i = bi & 511;
    #pragma unroll
    for (int jj = 0; jj < 2; jj++) {
        int j = tid + jj * 256;
        float2 r = ((const float2*)rp)[(size_t)bi * NN + j];
        char* hrow = smem + KB_H + j * 144;
        #pragma unroll 4
        for (int u = 0; u < 64; u += 2) {
            float h0 = fmaxf(0.f, fmaf(sw1[2 * u],     r.x, fmaf(sw1[2 * u + 1], r.y, sb1[u])));
            float h1 = fmaxf(0.f, fmaf(sw1[2 * u + 2], r.x, fmaf(sw1[2 * u + 3], r.y, sb1[u + 1])));
            *(uint32_t*)(hrow + u * 2) = packhf(h0, h1);
        }
    }
    __syncthreads();
    const uint32_t aOff = sbm + KB_H + (uint32_t)((wid * 64 + (lane & 15)) * 144
                                                  + ((lane >> 4) & 1) * 16);
    const uint32_t bAddr = sbm + KB_W2 + (uint32_t)(((lane & 7) + ((lane >> 4) & 1) * 8) * 144
                                                    + ((lane >> 3) & 1) * 16);
    float acc[4][2][4] = {};
    #pragma unroll
    for (int ks = 0; ks < 4; ks++) {
        uint32_t kc = ks * 32;
        uint32_t Bf[4];
        LDSM4(Bf, bAddr + kc);
        #pragma unroll
        for (int fm = 0; fm < 4; fm++) {
            uint32_t Af[4];
            LDSM4(Af, aOff + fm * 16 * 144 + kc);
            MMAF16(acc[fm][0], Af, &Bf[0]);
            MMAF16(acc[fm][1], Af, &Bf[2]);
        }
    }
    const int mrow = lane >> 2, ncol = (lane & 3) * 2;
    #pragma unroll
    for (int fm = 0; fm < 4; fm++)
        #pragma unroll
        for (int fn = 0; fn < 2; fn++)
            #pragma unroll
            for (int half = 0; half < 2; half++) {
                int j = wid * 64 + fm * 16 + mrow + half * 8;
                int hh = fn * 8 + ncol;
                float v0 = acc[fm][fn][half * 2 + 0] + sb2[hh];
                float v1 = acc[fm][fn][half * 2 + 1] + sb2[hh + 1];
                g_biasb[(((size_t)(b * HH + hh)     * NN) + i) * NN + j] = __float2bfloat16(v0);
                g_biasb[(((size_t)(b * HH + hh + 1) * NN) + i) * NN + j] = __float2bfloat16(v1);
            }
}

// ---------------- fused flash attention (online softmax) ------------------
#define FA3_SQH 0
#define FA3_SQL 9216
#define FA3_BUF 18432
#define FA3_KH 0
#define FA3_KL 18432
#define FA3_VF 36864
#define FA3_SB 55296
#define FA3_KBUF 72704
#define FA3_SM (18432 + 2*72704)
#define FA3_SMEM (FA3_SM + 2048)

__device__ __forceinline__ void fa_issue(uint32_t sb, int bh, int i0,
                                         int j0, uint32_t bufbase, int tid) {
    const __nv_bfloat16* kh = g_k_h + ((size_t)bh * NN + j0) * HD;
    const __nv_bfloat16* kl = g_k_l + ((size_t)bh * NN + j0) * HD;
    const unsigned short* vf = g_v_f + ((size_t)bh * NN + j0) * HD;
    for (int idx = tid; idx < 1024; idx += 128) {
        int row = idx >> 3, c = idx & 7;
        uint32_t so = bufbase + row * 144 + c * 16;
        size_t go = (size_t)row * HD;
        CP16(sb + FA3_KH + so, (const char*)(kh + go) + c * 16);
        CP16(sb + FA3_KL + so, (const char*)(kl + go) + c * 16);
        CP16(sb + FA3_VF + so, (const char*)(vf + go) + c * 16);
    }
    const __nv_bfloat16* bsrc = g_biasb + ((size_t)bh * NN + i0) * NN + j0;
    for (int idx = tid; idx < 1024; idx += 128) {
        int row = idx >> 4, c = idx & 15;
        CP16(sb + FA3_SB + bufbase + row * 272 + c * 16,
             (const char*)(bsrc + (size_t)row * NN) + c * 16);
    }
}

__global__ void __launch_bounds__(128, 1)
k_fa(const int* __restrict__ amask) {
    extern __shared__ char smem[];
    uint32_t sb = smem_u32(smem);
    const int tid = threadIdx.x, lane = tid & 31, wid = tid >> 5;
    const int bh = blockIdx.y, b = bh >> 4, h = bh & 15;
    const int i0 = blockIdx.x * 64;

    {
        const __nv_bfloat16* qh = g_q_h + ((size_t)bh * NN + i0) * HD;
        const __nv_bfloat16* ql = g_q_l + ((size_t)bh * NN + i0) * HD;
        for (int idx = tid; idx < 512; idx += 128) {
            int row = idx >> 3, c = idx & 7;
            CP16(sb + FA3_SQH + row * 144 + c * 16, (const char*)(qh + (size_t)row * HD) + c * 16);
            CP16(sb + FA3_SQL + row * 144 + c * 16, (const char*)(ql + (size_t)row * HD) + c * 16);
        }
        float* smask = (float*)(smem + FA3_SM);
        for (int j = tid; j < 512; j += 128)
            smask[j] = amask[b * NN + j] ? 0.f : -1e30f;
    }
    fa_issue(sb, bh, i0, 0, FA3_BUF, tid);
    CP_COMMIT();
    fa_issue(sb, bh, i0, 128, FA3_BUF + FA3_KBUF, tid);
    CP_COMMIT();

    const uint32_t aRow = (uint32_t)((wid * 16 + (lane & 15)) * 144 + ((lane >> 4) & 1) * 16);
    const uint32_t bRow = (uint32_t)(((lane & 7) + ((lane >> 4) & 1) * 8) * 144
                                     + ((lane >> 3) & 1) * 16);
    const uint32_t vRow = (uint32_t)(((lane & 7) + ((lane >> 3) & 1) * 8) * 144
                                     + ((lane >> 4) & 1) * 16);

    float oacc[8][4] = {};
    float rsum0 = 0.f, rsum1 = 0.f;
    float m0 = -1e30f, m1 = -1e30f;
    const float* smask = (const float*)(smem + FA3_SM);

    for (int j = 0; j < 4; j++) {
        const int j0 = j * 128;
        if (j < 3) CP_WAIT1(); else CP_WAIT0();
        __syncthreads();

        uint32_t kb0 = FA3_BUF + (j & 1) * FA3_KBUF;

        // ---- scores (bf16x3) ----
        float sacc[16][4] = {};
        #pragma unroll
        for (int ks = 0; ks < 4; ks++) {
            uint32_t kb = ks * 32;
            uint32_t qhf[4], qlf[4];
            LDSM4(qhf, sb + FA3_SQH + aRow + kb);
            LDSM4(qlf, sb + FA3_SQL + aRow + kb);
            #pragma unroll
            for (int pr = 0; pr < 8; pr++) {
                uint32_t kaddr = kb0 + bRow + pr * 16 * 144 + kb;
                uint32_t khf[4], klf[4];
                LDSM4(khf, sb + FA3_KH + kaddr);
                MMA16816(sacc[2 * pr + 0], qhf, &khf[0]);
                MMA16816(sacc[2 * pr + 1], qhf, &khf[2]);
                MMA16816(sacc[2 * pr + 0], qlf, &khf[0]);
                MMA16816(sacc[2 * pr + 1], qlf, &khf[2]);
                LDSM4(klf, sb + FA3_KL + kaddr);
                MMA16816(sacc[2 * pr + 0], qhf, &klf[0]);
                MMA16816(sacc[2 * pr + 1], qhf, &klf[2]);
            }
        }

        // ---- logits + online max ----
        const int rl0 = wid * 16 + (lane >> 2);
        const int cbase = (lane & 3) * 2;
        const char* bsb = smem + FA3_SB + kb0;
        float tm0 = -1e30f, tm1 = -1e30f;
        #pragma unroll
        for (int nt = 0; nt < 16; nt++) {
            int cl = nt * 8 + cbase;
            uint32_t b0raw = *(const uint32_t*)(bsb + (rl0)     * 272 + cl * 2);
            uint32_t b1raw = *(const uint32_t*)(bsb + (rl0 + 8) * 272 + cl * 2);
            __nv_bfloat162 bb0 = *reinterpret_cast<__nv_bfloat162*>(&b0raw);
            __nv_bfloat162 bb1 = *reinterpret_cast<__nv_bfloat162*>(&b1raw);
            float msk0 = smask[j0 + cl], msk1 = smask[j0 + cl + 1];
            sacc[nt][0] = sacc[nt][0] * 0.125f + __bfloat162float(bb0.x) + msk0;
            sacc[nt][1] = sacc[nt][1] * 0.125f + __bfloat162float(bb0.y) + msk1;
            sacc[nt][2] = sacc[nt][2] * 0.125f + __bfloat162float(bb1.x) + msk0;
            sacc[nt][3] = sacc[nt][3] * 0.125f + __bfloat162float(bb1.y) + msk1;
            tm0 = fmaxf(tm0, fmaxf(sacc[nt][0], sacc[nt][1]));
            tm1 = fmaxf(tm1, fmaxf(sacc[nt][2], sacc[nt][3]));
        }
        tm0 = fmaxf(tm0, __shfl_xor_sync(0xffffffffu, tm0, 1));
        tm0 = fmaxf(tm0, __shfl_xor_sync(0xffffffffu, tm0, 2));
        tm1 = fmaxf(tm1, __shfl_xor_sync(0xffffffffu, tm1, 1));
        tm1 = fmaxf(tm1, __shfl_xor_sync(0xffffffffu, tm1, 2));
        float nm0 = fmaxf(m0, tm0), nm1 = fmaxf(m1, tm1);
        float sc0 = __expf(m0 - nm0), sc1 = __expf(m1 - nm1);
        rsum0 *= sc0; rsum1 *= sc1;
        #pragma unroll
        for (int g = 0; g < 8; g++) {
            oacc[g][0] *= sc0; oacc[g][1] *= sc0;
            oacc[g][2] *= sc1; oacc[g][3] *= sc1;
        }
        m0 = nm0; m1 = nm1;

        // ---- exp(s - m) -> P fp16 fragments ----
        uint32_t ph[16][2];
        #pragma unroll
        for (int nt = 0; nt < 16; nt++) {
            float e0 = __expf(sacc[nt][0] - nm0);
            float e1 = __expf(sacc[nt][1] - nm0);
            float e2 = __expf(sacc[nt][2] - nm1);
            float e3 = __expf(sacc[nt][3] - nm1);
            rsum0 += e0 + e1; rsum1 += e2 + e3;
            ph[nt][0] = packhf(e0, e1);
            ph[nt][1] = packhf(e2, e3);
        }

        // ---- PV (fp16 1-pass) ----
        #pragma unroll
        for (int kk = 0; kk < 8; kk++) {
            uint32_t pa[4] = {ph[2*kk][0], ph[2*kk][1], ph[2*kk+1][0], ph[2*kk+1][1]};
            #pragma unroll
            for (int g = 0; g < 4; g++) {
                uint32_t vaddr = kb0 + vRow + kk * 16 * 144 + g * 32;
                uint32_t vf[4];
                LDSM4T(vf, sb + FA3_VF + vaddr);
                MMAF16(oacc[2 * g + 0], pa, &vf[0]);
                MMAF16(oacc[2 * g + 1], pa, &vf[2]);
            }
        }
        __syncthreads();
        if (j + 2 < 4)
            fa_issue(sb, bh, i0, (j + 2) * 128, FA3_BUF + (j & 1) * FA3_KBUF, tid);
        CP_COMMIT();
    }

    rsum0 += __shfl_xor_sync(0xffffffffu, rsum0, 1);
    rsum0 += __shfl_xor_sync(0xffffffffu, rsum0, 2);
    rsum1 += __shfl_xor_sync(0xffffffffu, rsum1, 1);
    rsum1 += __shfl_xor_sync(0xffffffffu, rsum1, 2);
    float inv0 = 1.f / rsum0, inv1 = 1.f / rsum1;
    const int r0 = i0 + wid * 16 + (lane >> 2);
    #pragma unroll
    for (int nt = 0; nt < 8; nt++) {
        int c = nt * 8 + (lane & 3) * 2;
        #pragma unroll
        for (int half = 0; half < 2; half++) {
            int gr = r0 + half * 8;
            float inv = half ? inv1 : inv0;
            float v0 = oacc[nt][half * 2 + 0] * inv;
            float v1 = oacc[nt][half * 2 + 1] * inv;
            size_t di = (size_t)(b * NN + gr) * DD + h * HD + c;
            *(uint32_t*)(g_ao_h + di) = packhf(v0, v1);
        }
    }
}

// ---------------- launch ----------------
extern "C" void kernel_launch(void* const* d_in, const int* in_sizes, int n_in,
                              void* d_out, int out_size) {
    (void)in_sizes; (void)n_in; (void)out_size;
    const float* x      = (const float*)d_in[0];
    const float* t_emb  = (const float*)d_in[1];
    const float* rp     = (const float*)d_in[2];
    const int*   amask  = (const int*)  d_in[3];
    const float* w_ada  = (const float*)d_in[4];
    const float* b_ada  = (const float*)d_in[5];
    const float* g1     = (const float*)d_in[6];
    const float* beta1  = (const float*)d_in[7];
    const float* g2     = (const float*)d_in[8];
    const float* beta2  = (const float*)d_in[9];
    const float* w_qkv  = (const float*)d_in[10];
    const float* b_qkv  = (const float*)d_in[11];
    const float* w_proj = (const float*)d_in[12];
    const float* b_proj = (const float*)d_in[13];
    const float* w_rp1  = (const float*)d_in[14];
    const float* b_rp1  = (const float*)d_in[15];
    const float* w_rp2  = (const float*)d_in[16];
    const float* b_rp2  = (const float*)d_in[17];
    const float* w_fc1  = (const float*)d_in[18];
    const float* b_fc1  = (const float*)d_in[19];
    const float* w_fc2  = (const float*)d_in[20];
    const float* b_fc2  = (const float*)d_in[21];
    float* out = (float*)d_out;

    cudaFuncSetAttribute(k_hmma2,  cudaFuncAttributeMaxDynamicSharedMemorySize, SMEM2);
    cudaFuncSetAttribute(k_hf16x1, cudaFuncAttributeMaxDynamicSharedMemorySize, SMEMX);
    cudaFuncSetAttribute(k_fa,     cudaFuncAttributeMaxDynamicSharedMemorySize, FA3_SMEM);
    cudaFuncSetAttribute(k_bias2,  cudaFuncAttributeMaxDynamicSharedMemorySize, KB_SMEM);

    void *p;
    unsigned short *xn_h, *xn_l, *xn_f, *ao_h, *hbuf, *wvf, *wpf, *w1f, *w2f;
    __nv_bfloat16 *wqk_h, *wqk_l;
    float *p_x1, *pt0, *pt1;
    cudaGetSymbolAddress(&p, g_xn_h);  xn_h = (unsigned short*)p;
    cudaGetSymbolAddress(&p, g_xn_l);  xn_l = (unsigned short*)p;
    cudaGetSymbolAddress(&p, g_xn_f);  xn_f = (unsigned short*)p;
    cudaGetSymbolAddress(&p, g_ao_h);  ao_h = (unsigned short*)p;
    cudaGetSymbolAddress(&p, g_hbuf);  hbuf = (unsigned short*)p;
    cudaGetSymbolAddress(&p, g_wqk_h); wqk_h = (__nv_bfloat16*)p;
    cudaGetSymbolAddress(&p, g_wqk_l); wqk_l = (__nv_bfloat16*)p;
    cudaGetSymbolAddress(&p, g_wv_f);  wvf  = (unsigned short*)p;
    cudaGetSymbolAddress(&p, g_wp_f);  wpf  = (unsigned short*)p;
    cudaGetSymbolAddress(&p, g_w1_f);  w1f  = (unsigned short*)p;
    cudaGetSymbolAddress(&p, g_w2_f);  w2f  = (unsigned short*)p;
    cudaGetSymbolAddress(&p, g_x1);    p_x1 = (float*)p;
    cudaGetSymbolAddress(&p, g_part0); pt0  = (float*)p;
    cudaGetSymbolAddress(&p, g_part1); pt1  = (float*)p;

    // side stream (created per call; harness calls only for correctness+capture)
    cudaStream_t s1;
    cudaEvent_t e0, e1, e2;
    cudaStreamCreateWithFlags(&s1, cudaStreamNonBlocking);
    cudaEventCreateWithFlags(&e0, cudaEventDisableTiming);
    cudaEventCreateWithFlags(&e1, cudaEventDisableTiming);
    cudaEventCreateWithFlags(&e2, cudaEventDisableTiming);

    // fork: bias MLP is independent of everything until k_fa
    cudaEventRecord(e0, 0);
    cudaStreamWaitEvent(s1, e0, 0);
    k_bias2<<<BB * NN, 256, KB_SMEM, s1>>>(rp, w_rp1, b_rp1, w_rp2, b_rp2);

    // main stream: modulation chain + conversions
    k_silu<<<16, 256>>>(t_emb);
    k_mod<<<(BB * MODD * 32 + 255) / 256, 256>>>(w_ada, b_ada);
    k_ln_mod<<<TOK, 256>>>(x, g1, beta1, 0, DD, xn_h, xn_l, xn_f);
    k_cvtall<<<2048, 256>>>((const float4*)w_qkv, (const float4*)w_proj,
                            (const float4*)w_fc1, (const float4*)w_fc2);
    cudaEventRecord(e2, 0);

    // Q,K projection (bf16x3, N=2048, 128 CTAs) on main stream
    k_hmma2<<<dim3(2*DD/128, TOK/256, 1), 512, SMEM2>>>(
        (const __nv_bfloat16*)xn_h, (const __nv_bfloat16*)xn_l, wqk_h, wqk_l,
        b_qkv, DD, 2*DD);

    // V projection on side stream (fills QK's idle SMs); needs ln1 + cvt
    cudaStreamWaitEvent(s1, e2, 0);
    k_hf16x1<<<dim3(DD/128, TOK/256, 1), 512, SMEMX, s1>>>(
        xn_f, wvf, b_qkv + 2*DD, nullptr, nullptr, nullptr, DD, DD, DD, 5);
    cudaEventRecord(e1, s1);

    // join: flash attention needs QK (main) + V + bias (s1)
    cudaStreamWaitEvent(0, e1, 0);
    k_fa<<<dim3(8, BB * HH), 128, FA3_SMEM>>>(amask);

    // proj (fp16 1-pass, split-K 2, 128 CTAs) + fused combine+LN2
    k_hf16x1<<<dim3(DD/128, TOK/256, 2), 512, SMEMX>>>(
        ao_h, wpf, nullptr, pt0, pt1, nullptr, DD, DD/2, DD, 4);
    k_comb_ln<<<TOK, 256>>>((const float4*)pt0, (const float4*)pt1,
                            b_proj, (const float4*)x, 2*DD,
                            g2, beta2, 3*DD, 4*DD,
                            (float4*)p_x1, xn_h);

    // fc1 gelu (fp16 1-pass)
    k_hf16x1<<<dim3(HID/128, TOK/256, 1), 512, SMEMX>>>(
        xn_h, w1f, b_fc1, nullptr, nullptr, hbuf, DD, DD, HID, 2);

    // fc2 (fp16 1-pass, split-K 2, 128 CTAs) + final combine
    k_hf16x1<<<dim3(DD/128, TOK/256, 2), 512, SMEMX>>>(
        hbuf, w2f, nullptr, pt0, pt1, nullptr, HID, HID/2, DD, 4);
    k_comb2<<<TOK*DD/4/256, 256>>>((const float4*)pt0, (const float4*)pt1,
                                   b_fc2, (const float4*)p_x1, 5*DD, (float4*)out);
}